// round 1
// baseline (speedup 1.0000x reference)
#include <cuda_runtime.h>

#define NQ        12
#define DIM       4096     // 2^12
#define NTHREADS  256
#define NCLS      10
#define NFEAT     36

// Fused gate parameters, computed once per launch by prep_kernel.
struct GateParams {
    float2 u[24][4];   // fused Rz*Ry*Rx per (layer*12 + wire): u00,u01,u10,u11
    float2 crx[24];    // (cos(th/2), sin(th/2)) in application order per layer
};
__device__ GateParams g_params;

__device__ __forceinline__ float2 cmul(float2 a, float2 b) {
    return make_float2(a.x * b.x - a.y * b.y, a.x * b.y + a.y * b.x);
}

// ---------------------------------------------------------------------------
// Prep: 96 angles -> 24 fused 1q matrices + 24 CRX (c,s) pairs
// Tape layout: layer*48 + [0:12)=rx, [12:24)=ry, [24:36)=rz, [36:48)=crx ring
// Layer 0 ring order: k -> crx(k, k+1 mod 12), angle = angles[36+k]
// Layer 1 ring order: k -> crx(11-k, 12-k mod 12), angle = angles[84+k]
// ---------------------------------------------------------------------------
__global__ void prep_kernel(const float* __restrict__ angles) {
    int t = threadIdx.x;
    if (t >= 24) return;
    int layer = t / 12, w = t % 12;

    float ax = angles[layer * 48 + w];
    float ay = angles[layer * 48 + 12 + w];
    float az = angles[layer * 48 + 24 + w];
    float sx, cx, sy, cy, sz, cz;
    sincosf(0.5f * ax, &sx, &cx);
    sincosf(0.5f * ay, &sy, &cy);
    sincosf(0.5f * az, &sz, &cz);

    // A = Ry * Rx
    float2 A00 = make_float2( cy * cx,  sy * sx);
    float2 A01 = make_float2(-sy * cx, -cy * sx);
    float2 A10 = make_float2( sy * cx, -cy * sx);
    float2 A11 = make_float2( cy * cx, -sy * sx);
    // U = Rz * A : row0 *= e^{-i az/2}, row1 *= e^{+i az/2}
    float2 e0 = make_float2(cz, -sz);
    float2 e1 = make_float2(cz,  sz);
    g_params.u[t][0] = cmul(e0, A00);
    g_params.u[t][1] = cmul(e0, A01);
    g_params.u[t][2] = cmul(e1, A10);
    g_params.u[t][3] = cmul(e1, A11);

    int gidx = (layer == 0) ? (36 + w) : (84 + w);  // application-order angle
    float th = angles[gidx];
    float s, c;
    sincosf(0.5f * th, &s, &c);
    g_params.crx[t] = make_float2(c, s);
}

// ---------------------------------------------------------------------------
// Main: one block per batch element, full state resident in SMEM.
// Wire w (PennyLane axis order) <-> bit b = 11 - w, stride s = 1<<b.
// ---------------------------------------------------------------------------
__global__ void __launch_bounds__(NTHREADS)
sim_kernel(const float* __restrict__ sv, const float* __restrict__ W,
           const float* __restrict__ bias, float* __restrict__ out) {
    __shared__ float2 amp[DIM];          // 32 KB
    __shared__ float red[8][3];
    __shared__ float feats[NFEAT];

    const int tid = threadIdx.x;
    const int bid = blockIdx.x;

    // ---- load real state vector (coalesced float4), imag = 0 ----
    const float4* src = (const float4*)(sv + (size_t)bid * DIM);
#pragma unroll
    for (int k = 0; k < 4; ++k) {
        float4 v = src[tid + k * NTHREADS];
        int base = 4 * (tid + k * NTHREADS);
        amp[base + 0] = make_float2(v.x, 0.f);
        amp[base + 1] = make_float2(v.y, 0.f);
        amp[base + 2] = make_float2(v.z, 0.f);
        amp[base + 3] = make_float2(v.w, 0.f);
    }
    __syncthreads();

#pragma unroll
    for (int layer = 0; layer < 2; ++layer) {
        // ---- 12 fused single-qubit gates ----
        for (int w = 0; w < 12; ++w) {
            const int b = 11 - w;
            const int s = 1 << b;
            const float2 u00 = g_params.u[layer * 12 + w][0];
            const float2 u01 = g_params.u[layer * 12 + w][1];
            const float2 u10 = g_params.u[layer * 12 + w][2];
            const float2 u11 = g_params.u[layer * 12 + w][3];
#pragma unroll
            for (int p = 0; p < 8; ++p) {
                int j  = tid + p * NTHREADS;               // pair index 0..2047
                int a0 = ((j >> b) << (b + 1)) | (j & (s - 1));
                int a1 = a0 | s;
                float2 z0 = amp[a0], z1 = amp[a1];
                float2 n0, n1;
                n0.x = u00.x * z0.x - u00.y * z0.y + u01.x * z1.x - u01.y * z1.y;
                n0.y = u00.x * z0.y + u00.y * z0.x + u01.x * z1.y + u01.y * z1.x;
                n1.x = u10.x * z0.x - u10.y * z0.y + u11.x * z1.x - u11.y * z1.y;
                n1.y = u10.x * z0.y + u10.y * z0.x + u11.x * z1.y + u11.y * z1.x;
                amp[a0] = n0;
                amp[a1] = n1;
            }
            __syncthreads();
        }
        // ---- CRX ring (sequential: adjacent gates share wires) ----
        for (int k = 0; k < 12; ++k) {
            const int c  = (layer == 0) ? k : 11 - k;
            const int t  = (c + 1) % 12;
            const int bc = 11 - c, bt = 11 - t;
            const int blo = bc < bt ? bc : bt;
            const int bhi = bc < bt ? bt : bc;
            const float2 cs = g_params.crx[layer * 12 + k];
#pragma unroll
            for (int p = 0; p < 4; ++p) {
                int j = tid + p * NTHREADS;                // 0..1023
                int idx = ((j >> blo) << (blo + 1)) | (j & ((1 << blo) - 1));
                idx = ((idx >> bhi) << (bhi + 1)) | (idx & ((1 << bhi) - 1));
                int a0 = idx | (1 << bc);                  // control = 1, target = 0
                int a1 = a0 | (1 << bt);                   // control = 1, target = 1
                float2 z0 = amp[a0], z1 = amp[a1];
                float2 n0, n1;
                // RX on target within control=1 subspace:
                // n0 = c*z0 - i s*z1 ; n1 = -i s*z0 + c*z1
                n0.x = cs.x * z0.x + cs.y * z1.y;
                n0.y = cs.x * z0.y - cs.y * z1.x;
                n1.x = cs.x * z1.x + cs.y * z0.y;
                n1.y = cs.x * z1.y - cs.y * z0.x;
                amp[a0] = n0;
                amp[a1] = n1;
            }
            __syncthreads();
        }
    }

    // ---- expectation values <X_q>, <Y_q>, <Z_q> ----
    const int wid = tid >> 5, lane = tid & 31;
    for (int q = 0; q < 12; ++q) {
        const int b = 11 - q;
        const int s = 1 << b;
        float z = 0.f, cr = 0.f, ci = 0.f;
#pragma unroll
        for (int p = 0; p < 8; ++p) {
            int j  = tid + p * NTHREADS;
            int a0 = ((j >> b) << (b + 1)) | (j & (s - 1));
            int a1 = a0 | s;
            float2 z0 = amp[a0], z1 = amp[a1];
            z  += z0.x * z0.x + z0.y * z0.y - z1.x * z1.x - z1.y * z1.y;
            cr += z0.x * z1.x + z0.y * z1.y;               // Re(conj(z0)*z1)
            ci += z0.x * z1.y - z0.y * z1.x;               // Im(conj(z0)*z1)
        }
#pragma unroll
        for (int o = 16; o; o >>= 1) {
            z  += __shfl_xor_sync(0xffffffffu, z,  o);
            cr += __shfl_xor_sync(0xffffffffu, cr, o);
            ci += __shfl_xor_sync(0xffffffffu, ci, o);
        }
        if (lane == 0) { red[wid][0] = cr; red[wid][1] = ci; red[wid][2] = z; }
        __syncthreads();
        if (tid == 0) {
            float tc = 0.f, ti = 0.f, tz = 0.f;
#pragma unroll
            for (int ww = 0; ww < 8; ++ww) {
                tc += red[ww][0]; ti += red[ww][1]; tz += red[ww][2];
            }
            feats[q]      = 2.f * tc;   // <X_q>
            feats[12 + q] = 2.f * ti;   // <Y_q>
            feats[24 + q] = tz;         // <Z_q>
        }
        __syncthreads();
    }

    // ---- linear head: out = feats @ W.T + b ----
    if (tid < NCLS) {
        float acc = bias[tid];
#pragma unroll
        for (int f = 0; f < NFEAT; ++f) acc += W[tid * NFEAT + f] * feats[f];
        out[bid * NCLS + tid] = acc;
    }
}

extern "C" void kernel_launch(void* const* d_in, const int* in_sizes, int n_in,
                              void* d_out, int out_size) {
    const float* sv     = (const float*)d_in[0];
    const float* angles = (const float*)d_in[1];
    const float* W      = (const float*)d_in[2];
    const float* b      = (const float*)d_in[3];
    float* out          = (float*)d_out;

    int batch = in_sizes[0] / DIM;
    prep_kernel<<<1, 32>>>(angles);
    sim_kernel<<<batch, NTHREADS>>>(sv, W, b, out);
}

// round 3
// speedup vs baseline: 1.6142x; 1.6142x over previous
#include <cuda_runtime.h>

#define NQ        12
#define DIM       4096
#define NTHREADS  256
#define NCLS      10
#define NFEAT     36

// Fused gate parameters, computed once per launch by prep_kernel.
struct GateParams {
    float2 u[24][4];   // fused Rz*Ry*Rx per (layer*12 + wire): u00,u01,u10,u11
    float2 crx[24];    // (cos(th/2), sin(th/2)) in application order per layer
};
__device__ GateParams g_params;

__device__ __forceinline__ float2 cmul(float2 a, float2 b) {
    return make_float2(a.x * b.x - a.y * b.y, a.x * b.y + a.y * b.x);
}

// ---------------------------------------------------------------------------
// Prep: 96 angles -> 24 fused 1q matrices + 24 CRX (c,s) pairs
// ---------------------------------------------------------------------------
__global__ void prep_kernel(const float* __restrict__ angles) {
    int t = threadIdx.x;
    if (t >= 24) return;
    int layer = t / 12, w = t % 12;

    float ax = angles[layer * 48 + w];
    float ay = angles[layer * 48 + 12 + w];
    float az = angles[layer * 48 + 24 + w];
    float sx, cx, sy, cy, sz, cz;
    sincosf(0.5f * ax, &sx, &cx);
    sincosf(0.5f * ay, &sy, &cy);
    sincosf(0.5f * az, &sz, &cz);

    float2 A00 = make_float2( cy * cx,  sy * sx);
    float2 A01 = make_float2(-sy * cx, -cy * sx);
    float2 A10 = make_float2( sy * cx, -cy * sx);
    float2 A11 = make_float2( cy * cx, -sy * sx);
    float2 e0 = make_float2(cz, -sz);
    float2 e1 = make_float2(cz,  sz);
    g_params.u[t][0] = cmul(e0, A00);
    g_params.u[t][1] = cmul(e0, A01);
    g_params.u[t][2] = cmul(e1, A10);
    g_params.u[t][3] = cmul(e1, A11);

    int gidx = (layer == 0) ? (36 + w) : (84 + w);
    float th = angles[gidx];
    float s, c;
    sincosf(0.5f * th, &s, &c);
    g_params.crx[t] = make_float2(c, s);
}

// ---------------------------------------------------------------------------
// Register-resident simulator.
// Amp index i (12 bits) = [tid(8 bits) << 4] | r(4 bits).
//   bits 0-3  : local register index r
//   bits 4-8  : lane bits (tid bits 0-4)
//   bits 9-11 : warp bits (tid bits 5-7)
// SMEM buffer layout buf[r*256 + tid] -> conflict-free LDS.64/STS.64.
// ---------------------------------------------------------------------------

__device__ __forceinline__ void mul1q(float2& o, float2 cm, float2 zm, float2 cp, float2 zp) {
    o.x = cm.x * zm.x - cm.y * zm.y + cp.x * zp.x - cp.y * zp.y;
    o.y = cm.x * zm.y + cm.y * zm.x + cp.x * zp.y + cp.y * zp.x;
}

// CRX (control=1 subspace): n = c*z + s*J(partner), J(p) = (p.y, -p.x)
__device__ __forceinline__ void crx_upd(float2& zm, float2 zp, float2 cs) {
    float2 n;
    n.x = cs.x * zm.x + cs.y * zp.y;
    n.y = cs.x * zm.y - cs.y * zp.x;
    zm = n;
}

template<int B>
__device__ __forceinline__ void g1_local(float2 a[16], const float2* u) {
    float2 u00 = u[0], u01 = u[1], u10 = u[2], u11 = u[3];
#pragma unroll
    for (int r = 0; r < 16; ++r) {
        if (r & (1 << B)) continue;
        int r1 = r | (1 << B);
        float2 z0 = a[r], z1 = a[r1], n0, n1;
        mul1q(n0, u00, z0, u01, z1);
        mul1q(n1, u10, z0, u11, z1);
        a[r] = n0; a[r1] = n1;
    }
}

template<int B>
__device__ __forceinline__ void g1_lane(float2 a[16], const float2* u, int tid) {
    const int m = 1 << (B - 4);
    const bool hi = (tid >> (B - 4)) & 1;
    float2 u00 = u[0], u01 = u[1], u10 = u[2], u11 = u[3];
    float2 cm = hi ? u11 : u00;
    float2 cp = hi ? u10 : u01;
#pragma unroll
    for (int r = 0; r < 16; ++r) {
        float2 p;
        p.x = __shfl_xor_sync(0xffffffffu, a[r].x, m);
        p.y = __shfl_xor_sync(0xffffffffu, a[r].y, m);
        float2 n;
        mul1q(n, cm, a[r], cp, p);
        a[r] = n;
    }
}

template<int B>
__device__ __forceinline__ void g1_warp(float2 a[16], const float2* u, int tid, float2* buf) {
    __syncthreads();
#pragma unroll
    for (int r = 0; r < 16; ++r) buf[r * NTHREADS + tid] = a[r];
    __syncthreads();
    const int pt = tid ^ (1 << (B - 4));
    const bool hi = (tid >> (B - 4)) & 1;
    float2 u00 = u[0], u01 = u[1], u10 = u[2], u11 = u[3];
    float2 cm = hi ? u11 : u00;
    float2 cp = hi ? u10 : u01;
#pragma unroll
    for (int r = 0; r < 16; ++r) {
        float2 p = buf[r * NTHREADS + pt];
        float2 n;
        mul1q(n, cm, a[r], cp, p);
        a[r] = n;
    }
}

template<int BC, int BT>
__device__ __forceinline__ void crx_gate(float2 a[16], float2 cs, int tid, float2* buf) {
    if constexpr (BT < 4) {
        // target bit local
        if constexpr (BC < 4) {
#pragma unroll
            for (int r = 0; r < 16; ++r) {
                if (!((r >> BC) & 1) || ((r >> BT) & 1)) continue;
                int r1 = r | (1 << BT);
                float2 z0 = a[r], z1 = a[r1];
                crx_upd(a[r], z1, cs);
                crx_upd(a[r1], z0, cs);
            }
        } else {
            bool ctrl = (tid >> (BC - 4)) & 1;
            if (ctrl) {
#pragma unroll
                for (int r = 0; r < 16; ++r) {
                    if ((r >> BT) & 1) continue;
                    int r1 = r | (1 << BT);
                    float2 z0 = a[r], z1 = a[r1];
                    crx_upd(a[r], z1, cs);
                    crx_upd(a[r1], z0, cs);
                }
            }
        }
    } else if constexpr (BT < 9) {
        // target bit in lane bits
        const int m = 1 << (BT - 4);
        if constexpr (BC < 4) {
#pragma unroll
            for (int r = 0; r < 16; ++r) {
                if (!((r >> BC) & 1)) continue;
                float2 p;
                p.x = __shfl_xor_sync(0xffffffffu, a[r].x, m);
                p.y = __shfl_xor_sync(0xffffffffu, a[r].y, m);
                crx_upd(a[r], p, cs);
            }
        } else {
            bool ctrl = (tid >> (BC - 4)) & 1;
#pragma unroll
            for (int r = 0; r < 16; ++r) {
                float2 p;
                p.x = __shfl_xor_sync(0xffffffffu, a[r].x, m);
                p.y = __shfl_xor_sync(0xffffffffu, a[r].y, m);
                if (ctrl) crx_upd(a[r], p, cs);
            }
        }
    } else {
        // target bit in warp bits: smem exchange
        __syncthreads();
#pragma unroll
        for (int r = 0; r < 16; ++r) buf[r * NTHREADS + tid] = a[r];
        __syncthreads();
        const int pt = tid ^ (1 << (BT - 4));
        if constexpr (BC < 4) {
#pragma unroll
            for (int r = 0; r < 16; ++r) {
                if (!((r >> BC) & 1)) continue;
                float2 p = buf[r * NTHREADS + pt];
                crx_upd(a[r], p, cs);
            }
        } else {
            bool ctrl = (tid >> (BC - 4)) & 1;
            if (ctrl) {
#pragma unroll
                for (int r = 0; r < 16; ++r) {
                    float2 p = buf[r * NTHREADS + pt];
                    crx_upd(a[r], p, cs);
                }
            }
        }
    }
}

template<int L>
__device__ __forceinline__ void apply_layer(float2 a[16], int tid, float2* buf) {
    // 12 fused single-qubit gates: wire w -> bit 11-w
    g1_warp<11>(a, g_params.u[L * 12 + 0], tid, buf);
    g1_warp<10>(a, g_params.u[L * 12 + 1], tid, buf);
    g1_warp<9> (a, g_params.u[L * 12 + 2], tid, buf);
    g1_lane<8> (a, g_params.u[L * 12 + 3], tid);
    g1_lane<7> (a, g_params.u[L * 12 + 4], tid);
    g1_lane<6> (a, g_params.u[L * 12 + 5], tid);
    g1_lane<5> (a, g_params.u[L * 12 + 6], tid);
    g1_lane<4> (a, g_params.u[L * 12 + 7], tid);
    g1_local<3>(a, g_params.u[L * 12 + 8]);
    g1_local<2>(a, g_params.u[L * 12 + 9]);
    g1_local<1>(a, g_params.u[L * 12 + 10]);
    g1_local<0>(a, g_params.u[L * 12 + 11]);

    // CRX ring (order matters)
    if constexpr (L == 0) {
        crx_gate<11, 10>(a, g_params.crx[0],  tid, buf);
        crx_gate<10, 9> (a, g_params.crx[1],  tid, buf);
        crx_gate<9, 8>  (a, g_params.crx[2],  tid, buf);
        crx_gate<8, 7>  (a, g_params.crx[3],  tid, buf);
        crx_gate<7, 6>  (a, g_params.crx[4],  tid, buf);
        crx_gate<6, 5>  (a, g_params.crx[5],  tid, buf);
        crx_gate<5, 4>  (a, g_params.crx[6],  tid, buf);
        crx_gate<4, 3>  (a, g_params.crx[7],  tid, buf);
        crx_gate<3, 2>  (a, g_params.crx[8],  tid, buf);
        crx_gate<2, 1>  (a, g_params.crx[9],  tid, buf);
        crx_gate<1, 0>  (a, g_params.crx[10], tid, buf);
        crx_gate<0, 11> (a, g_params.crx[11], tid, buf);
    } else {
        crx_gate<0, 11> (a, g_params.crx[12], tid, buf);
        crx_gate<1, 0>  (a, g_params.crx[13], tid, buf);
        crx_gate<2, 1>  (a, g_params.crx[14], tid, buf);
        crx_gate<3, 2>  (a, g_params.crx[15], tid, buf);
        crx_gate<4, 3>  (a, g_params.crx[16], tid, buf);
        crx_gate<5, 4>  (a, g_params.crx[17], tid, buf);
        crx_gate<6, 5>  (a, g_params.crx[18], tid, buf);
        crx_gate<7, 6>  (a, g_params.crx[19], tid, buf);
        crx_gate<8, 7>  (a, g_params.crx[20], tid, buf);
        crx_gate<9, 8>  (a, g_params.crx[21], tid, buf);
        crx_gate<10, 9> (a, g_params.crx[22], tid, buf);
        crx_gate<11, 10>(a, g_params.crx[23], tid, buf);
    }
}

template<int B>
__device__ __forceinline__ void expval_bit(const float2 a[16], int tid, const float2* buf,
                                           float& X, float& Y, float& Z) {
    X = 0.f; Y = 0.f; Z = 0.f;
    if constexpr (B < 4) {
#pragma unroll
        for (int r = 0; r < 16; ++r) {
            if ((r >> B) & 1) continue;
            int r1 = r | (1 << B);
            float2 z0 = a[r], z1 = a[r1];
            X += 2.f * (z0.x * z1.x + z0.y * z1.y);
            Y += 2.f * (z0.x * z1.y - z0.y * z1.x);
            Z += (z0.x * z0.x + z0.y * z0.y) - (z1.x * z1.x + z1.y * z1.y);
        }
    } else if constexpr (B < 9) {
        const int m = 1 << (B - 4);
        const float sgn = ((tid >> (B - 4)) & 1) ? -1.f : 1.f;
#pragma unroll
        for (int r = 0; r < 16; ++r) {
            float2 p;
            p.x = __shfl_xor_sync(0xffffffffu, a[r].x, m);
            p.y = __shfl_xor_sync(0xffffffffu, a[r].y, m);
            X += a[r].x * p.x + a[r].y * p.y;
            Y += sgn * (a[r].x * p.y - a[r].y * p.x);
            Z += sgn * (a[r].x * a[r].x + a[r].y * a[r].y);
        }
    } else {
        const int pt = tid ^ (1 << (B - 4));
        const float sgn = ((tid >> (B - 4)) & 1) ? -1.f : 1.f;
#pragma unroll
        for (int r = 0; r < 16; ++r) {
            float2 p = buf[r * NTHREADS + pt];
            X += a[r].x * p.x + a[r].y * p.y;
            Y += sgn * (a[r].x * p.y - a[r].y * p.x);
            Z += sgn * (a[r].x * a[r].x + a[r].y * a[r].y);
        }
    }
}

template<int Q>
__device__ __forceinline__ void do_expval(const float2 a[16], int tid, const float2* buf,
                                          float red[12][8][3]) {
    constexpr int B = 11 - Q;
    float X, Y, Z;
    expval_bit<B>(a, tid, buf, X, Y, Z);
#pragma unroll
    for (int o = 16; o; o >>= 1) {
        X += __shfl_xor_sync(0xffffffffu, X, o);
        Y += __shfl_xor_sync(0xffffffffu, Y, o);
        Z += __shfl_xor_sync(0xffffffffu, Z, o);
    }
    if ((tid & 31) == 0) {
        int w = tid >> 5;
        red[Q][w][0] = X;
        red[Q][w][1] = Y;
        red[Q][w][2] = Z;
    }
}

__global__ void __launch_bounds__(NTHREADS, 2)
sim_kernel(const float* __restrict__ sv, const float* __restrict__ W,
           const float* __restrict__ bias, float* __restrict__ out) {
    __shared__ float2 buf[DIM];          // 32 KB exchange buffer, layout [r][tid]
    __shared__ float red[12][8][3];
    __shared__ float feats[NFEAT];

    const int tid = threadIdx.x;
    const int bid = blockIdx.x;

    float2 a[16];

    // ---- load: thread holds amps i = tid*16 + r, input is real ----
    const float4* src = (const float4*)(sv + (size_t)bid * DIM) + tid * 4;
#pragma unroll
    for (int k = 0; k < 4; ++k) {
        float4 v = src[k];
        a[4 * k + 0] = make_float2(v.x, 0.f);
        a[4 * k + 1] = make_float2(v.y, 0.f);
        a[4 * k + 2] = make_float2(v.z, 0.f);
        a[4 * k + 3] = make_float2(v.w, 0.f);
    }

    apply_layer<0>(a, tid, buf);
    apply_layer<1>(a, tid, buf);

    // ---- store state once for warp-bit expval cross terms ----
    __syncthreads();
#pragma unroll
    for (int r = 0; r < 16; ++r) buf[r * NTHREADS + tid] = a[r];
    __syncthreads();

    do_expval<0>(a, tid, buf, red);
    do_expval<1>(a, tid, buf, red);
    do_expval<2>(a, tid, buf, red);
    do_expval<3>(a, tid, buf, red);
    do_expval<4>(a, tid, buf, red);
    do_expval<5>(a, tid, buf, red);
    do_expval<6>(a, tid, buf, red);
    do_expval<7>(a, tid, buf, red);
    do_expval<8>(a, tid, buf, red);
    do_expval<9>(a, tid, buf, red);
    do_expval<10>(a, tid, buf, red);
    do_expval<11>(a, tid, buf, red);
    __syncthreads();

    if (tid < NFEAT) {
        int q = tid % 12, comp = tid / 12;
        float s = 0.f;
#pragma unroll
        for (int w = 0; w < 8; ++w) s += red[q][w][comp];
        feats[comp * 12 + q] = s;    // X block, Y block, Z block
    }
    __syncthreads();

    if (tid < NCLS) {
        float acc = bias[tid];
#pragma unroll
        for (int f = 0; f < NFEAT; ++f) acc += W[tid * NFEAT + f] * feats[f];
        out[bid * NCLS + tid] = acc;
    }
}

extern "C" void kernel_launch(void* const* d_in, const int* in_sizes, int n_in,
                              void* d_out, int out_size) {
    const float* sv     = (const float*)d_in[0];
    const float* angles = (const float*)d_in[1];
    const float* W      = (const float*)d_in[2];
    const float* b      = (const float*)d_in[3];
    float* out          = (float*)d_out;

    int batch = in_sizes[0] / DIM;
    prep_kernel<<<1, 32>>>(angles);
    sim_kernel<<<batch, NTHREADS>>>(sv, W, b, out);
}